// round 9
// baseline (speedup 1.0000x reference)
#include <cuda_runtime.h>
#include <cuda_bf16.h>
#include <stdint.h>

// PositionEncoding: out[pos][64] = is_class ? E_class[cid[pos]] : sincos(values[pos])
// sincos dim 2i = sin(2^i*pi*v), 2i+1 = cos(2^i*pi*v); fp32 angle is exactly
// 2^i * fl(v*pi_f) (power-of-2 scaling exact) -> 64-bit fixed-point reduction.
//
// R7-R9: UNROLL 4->8 (amortize the two serialized load-latency waves over 2x work)
// and predicate the E gather on is_class (halves gather L1/L2 wavefronts).
// Stores remain perfectly coalesced float4.

#define NPOS      (64 * 8192)            // B * S
#define NTHREADS  (NPOS * 16)
#define UNROLL    8
#define GSIZE     (NTHREADS / UNROLL)    // 1,048,576 (divisible by 16)
#define PSTRIDE   (GSIZE / 16)           // 65,536: position stride between iters

__global__ __launch_bounds__(256)
void pe_kernel(const float*  __restrict__ values,
               const float4* __restrict__ E,        // [4096][16] float4
               const int*    __restrict__ cid,
               const int*    __restrict__ isc,
               float4*       __restrict__ out)      // [NPOS][16] float4
{
    const int g       = blockIdx.x * blockDim.x + threadIdx.x;
    const int chunk   = g & 15;          // same chunk all iters (GSIZE % 16 == 0)
    const int lvl     = chunk << 1;
    const int posBase = g >> 4;

    int   iv [UNROLL];
    float vv [UNROLL];
    int   cv [UNROLL];

    // ---- phase 1: all independent scalar loads in flight (MLP ~24) ----
    #pragma unroll
    for (int i = 0; i < UNROLL; i++) {
        const int p = posBase + i * PSTRIDE;
        iv[i] = __ldg(&isc[p]);
        vv[i] = __ldg(&values[p]);
        cv[i] = __ldg(&cid[p]);
    }

    // ---- phase 2: PREDICATED E gathers (only class positions touch memory) ----
    float4 e[UNROLL];
    #pragma unroll
    for (int i = 0; i < UNROLL; i++) {
        e[i] = make_float4(0.f, 0.f, 0.f, 0.f);
        if (iv[i] != 0)
            e[i] = __ldg(&E[(size_t)cv[i] * 16 + chunk]);
    }

    // ---- phase 3: sincos + branchless select ----
    float4 r[UNROLL];
    #pragma unroll
    for (int i = 0; i < UNROLL; i++) {
        // theta = fl(v * pi_f), pi_f = 0x40490FDB
        const float th = vv[i] * __uint_as_float(0x40490FDBu);

        // u = frac(theta/(2pi)) in 64-bit fixed point, Q = floor(2^64/(2pi))
        const uint32_t b  = __float_as_uint(th);         // th >= 0
        const uint32_t ex = b >> 23;                     // biased exponent (<=128)
        const uint32_t m  = (b & 0x7FFFFFu) | (ex ? 0x800000u : 0u);
        const uint64_t p1 = (uint64_t)m * 0x9391054AULL; // m*Q_lo  (< 2^56)
        const uint64_t p2 = (uint64_t)m * 0x28BE60DBULL; // m*Q_hi  (< 2^54)
        const uint64_t U0 = (p2 << 10) + (p1 >> 22);     // (m*Q) >> 22
        const uint32_t sh = 128u - ex;
        const uint64_t u  = (sh < 64u) ? (U0 >> sh) : 0ULL;

        // anchor at level l = 2*chunk: frac(2^l*u), top 32b signed -> [-pi, pi)
        const uint64_t f   = u << lvl;
        const int32_t  ti  = (int32_t)(f >> 32);
        const float    ang = (float)ti * 1.4629180792671596e-9f;  // *2pi/2^32
        const float s0 = __sinf(ang);
        const float c0 = __cosf(ang);

        // one double-angle step for level l+1
        const float t2 = c0 + c0;
        const float c1 = fmaf(t2, c0, -1.0f);
        const float s1 = t2 * s0;

        const bool cls = (iv[i] != 0);
        r[i].x = cls ? e[i].x : s0;
        r[i].y = cls ? e[i].y : c0;
        r[i].z = cls ? e[i].z : s1;
        r[i].w = cls ? e[i].w : c1;
    }

    // ---- phase 4: coalesced float4 stores ----
    #pragma unroll
    for (int i = 0; i < UNROLL; i++)
        out[(size_t)(posBase + i * PSTRIDE) * 16 + chunk] = r[i];
}

extern "C" void kernel_launch(void* const* d_in, const int* in_sizes, int n_in,
                              void* d_out, int out_size)
{
    const float*  values = (const float*)d_in[0];
    const float4* E      = (const float4*)d_in[1];
    const int*    cids   = (const int*)d_in[2];
    const int*    isc    = (const int*)d_in[3];
    float4*       out    = (float4*)d_out;

    const int threads = 256;
    const int blocks  = GSIZE / threads;   // 4096
    pe_kernel<<<blocks, threads>>>(values, E, cids, isc, out);
}

// round 10
// speedup vs baseline: 1.3022x; 1.3022x over previous
#include <cuda_runtime.h>
#include <cuda_bf16.h>
#include <stdint.h>

// PositionEncoding: out[pos][64] = is_class ? E_class[cid[pos]] : sincos(values[pos])
// sincos dim 2i = sin(2^i*pi*v), 2i+1 = cos(2^i*pi*v); fp32 angle is exactly
// 2^i * fl(v*pi_f) -> 64-bit fixed-point reduction (Q = floor(2^64/2pi)).
//
// R10 restructure: one lane = one position for loads + reduction (coalesced
// 128B scalar loads, reduction computed once per position instead of 16x),
// then a 16-iter store loop redistributes (u_hi,u_lo,cid|cls) via shfl.
// Store iter k: lanes 0-15 -> pos 2k, lanes 16-31 -> pos 2k+1; lane's chunk
// angle = one funnel shift. Predicated E gather; coalesced float4 stores.

#define NPOS (64 * 8192)                 // B * S = 524288

__global__ __launch_bounds__(256)
void pe_kernel(const float*  __restrict__ values,
               const float4* __restrict__ E,        // [4096][16] float4
               const int*    __restrict__ cid,
               const int*    __restrict__ isc,
               float4*       __restrict__ out)      // [NPOS][16] float4
{
    const int tid     = blockIdx.x * blockDim.x + threadIdx.x;
    const int lane    = threadIdx.x & 31;
    const int basePos = (tid >> 5) << 5;    // this warp's 32 positions
    const int myPos   = basePos + lane;

    // ---- coalesced per-position scalar loads (one lane = one position) ----
    const int   iv = __ldg(&isc[myPos]);
    const float v  = __ldg(&values[myPos]);
    const int   cv = __ldg(&cid[myPos]);

    // ---- fixed-point reduction, ONCE per position ----
    // theta = fl(v * pi_f), pi_f = 0x40490FDB
    const float th = v * __uint_as_float(0x40490FDBu);
    const uint32_t b  = __float_as_uint(th);          // th >= 0
    const uint32_t ex = b >> 23;                      // biased exponent (<=128)
    const uint32_t m  = (b & 0x7FFFFFu) | (ex ? 0x800000u : 0u);
    const uint64_t p1 = (uint64_t)m * 0x9391054AULL;  // m*Q_lo  (< 2^56)
    const uint64_t p2 = (uint64_t)m * 0x28BE60DBULL;  // m*Q_hi  (< 2^54)
    const uint64_t U0 = (p2 << 10) + (p1 >> 22);      // (m*Q) >> 22
    const uint32_t sh = 128u - ex;
    const uint64_t u  = (sh < 64u) ? (U0 >> sh) : 0ULL;  // frac(th/2pi)*2^64

    const uint32_t u_lo = (uint32_t)u;
    const uint32_t u_hi = (uint32_t)(u >> 32);
    const uint32_t pk   = (uint32_t)cv | (iv ? 0x80000000u : 0u);  // cid | cls

    const int chunk = lane & 15;
    const int lvl   = chunk << 1;          // 0,2,...,30
    const int half  = lane >> 4;           // 0 or 1

    // ---- store loop: iter k covers positions basePos+2k (lanes 0-15)
    //      and basePos+2k+1 (lanes 16-31); stores are contiguous 512B ----
    #pragma unroll 4
    for (int k = 0; k < 16; k++) {
        const int j = 2 * k + half;        // source lane / local position

        const uint32_t uh = __shfl_sync(0xFFFFFFFFu, u_hi, j);
        const uint32_t ul = __shfl_sync(0xFFFFFFFFu, u_lo, j);
        const uint32_t pj = __shfl_sync(0xFFFFFFFFu, pk,   j);

        // frac(2^lvl * u): high word of (u << lvl), signed -> [-pi, pi)
        const int32_t ti  = (int32_t)__funnelshift_l(ul, uh, lvl);
        const float   ang = (float)ti * 1.4629180792671596e-9f;   // *2pi/2^32
        const float s0 = __sinf(ang);
        const float c0 = __cosf(ang);
        const float t2 = c0 + c0;
        const float c1 = fmaf(t2, c0, -1.0f);   // cos(2a)
        const float s1 = t2 * s0;               // sin(2a)

        float4 r = make_float4(s0, c0, s1, c1);
        if (pj & 0x80000000u)                   // class position: gather row
            r = __ldg(&E[(size_t)(pj & 0x7FFFFFFFu) * 16 + chunk]);

        out[(size_t)(basePos + j) * 16 + chunk] = r;
    }
}

extern "C" void kernel_launch(void* const* d_in, const int* in_sizes, int n_in,
                              void* d_out, int out_size)
{
    const float*  values = (const float*)d_in[0];
    const float4* E      = (const float4*)d_in[1];
    const int*    cids   = (const int*)d_in[2];
    const int*    isc    = (const int*)d_in[3];
    float4*       out    = (float4*)d_out;

    const int threads = 256;
    const int blocks  = NPOS / threads;    // 2048 blocks; 1 thread per position
    pe_kernel<<<blocks, threads>>>(values, E, cids, isc, out);
}